// round 1
// baseline (speedup 1.0000x reference)
#include <cuda_runtime.h>
#include <math.h>

// Born-Wolf PSF: params (16,64,2) -> psf (16,64,25,25,25), normalized.
// One block per (b,c) pair. Factored evaluation:
//   A[r][i]  = J0(k n R[r] rho_i) * rho_i * trapw_i          (35 x 101)
//   CS[z][i] = (cos, sin)(0.5 k n^2 rho_i^2 z)               (13 x 101)
//   plane[z][r] = (sum_i A*cos)^2 + (sum_i A*sin)^2          (tiny matmul)
// then reflect-pad in z + radial bilinear interp + normalize.

#define NHALF 13
#define NR    35
#define NI    101

// Accurate sincos for |x| up to ~1000: Cody-Waite 2-pi reduction, then __sincosf
// (accurate on [-pi,pi] regardless of -use_fast_math).
__device__ __forceinline__ void rsincos(float x, float* s, float* c) {
    float q = rintf(x * 0.15915494309189535f);      // x / (2*pi), |q| <= ~150
    float r = fmaf(q, -6.28125f, x);                 // hi part exact (few mantissa bits)
    r = fmaf(q, -1.9353071795864769e-3f, r);         // lo part
    __sincosf(r, s, c);
}

// Replicates the reference's Abramowitz&Stegun rational J0 in f32.
__device__ __forceinline__ float bessel_j0f(float x) {
    float ax = fabsf(x);
    if (ax <= 8.0f) {
        float y = x * x;
        float num = -184.9052456f;
        num = fmaf(num, y, 77392.33017f);
        num = fmaf(num, y, -11214424.18f);
        num = fmaf(num, y, 651619640.7f);
        num = fmaf(num, y, -13362590354.0f);
        num = fmaf(num, y, 57568490574.0f);
        float den = y + 267.8532712f;
        den = fmaf(den, y, 59272.64853f);
        den = fmaf(den, y, 9494680.718f);
        den = fmaf(den, y, 1029532985.0f);
        den = fmaf(den, y, 57568490411.0f);
        return num / den;
    } else {
        float z = 8.0f / ax;
        float y2 = z * z;
        float xx = ax - 0.785398164f;
        float p1 = 0.2093887211e-6f;
        p1 = fmaf(p1, y2, -0.2073370639e-5f);
        p1 = fmaf(p1, y2, 0.2734510407e-4f);
        p1 = fmaf(p1, y2, -0.1098628627e-2f);
        p1 = fmaf(p1, y2, 1.0f);
        float p2 = -0.934935152e-7f;
        p2 = fmaf(p2, y2, 0.7621095161e-6f);
        p2 = fmaf(p2, y2, -0.6911147651e-5f);
        p2 = fmaf(p2, y2, 0.1430488765e-3f);
        p2 = fmaf(p2, y2, -0.1562499995e-1f);
        float s, c;
        rsincos(xx, &s, &c);
        return sqrtf(0.636619772f / ax) * (c * p1 - z * s * p2);
    }
}

__global__ __launch_bounds__(256, 4)
void bw_psf_kernel(const float* __restrict__ params, float* __restrict__ out) {
    const int p = blockIdx.x;
    const int tid = threadIdx.x;

    __shared__ float  sA[NR][NI];        // 14.1 KB
    __shared__ float2 sCS[NHALF][NI];    // 10.5 KB
    __shared__ float  sPlane[NHALF][NR + 1];
    __shared__ float  sCol[NR + 1];
    __shared__ float  sRed[8];
    __shared__ float  sInv;

    const float lam = fabsf(params[2 * p]);
    const float n   = fabsf(params[2 * p + 1]);
    const float k   = 6.2831853071795864769f / lam;
    const float kn  = k * n;
    const float kz2 = 0.5f * k * n * n;

    // ---- Phase 1: A[r][i] = J0(kn * (r/2) * rho_i) * rho_i * trapw_i ----
    for (int idx = tid; idx < NR * NI; idx += 256) {
        int r = idx / NI, i = idx - r * NI;
        float rho = (float)i * 0.01f;
        float arg = kn * (0.5f * (float)r) * rho;
        float tw  = (i == 0 || i == NI - 1) ? 0.005f : 0.01f;  // trapezoid weight * DX
        sA[r][i] = bessel_j0f(arg) * rho * tw;
    }
    // ---- Phase 2: CS[z][i] = (cos w, sin w), w = kz2 * rho^2 * z ----
    for (int idx = tid; idx < NHALF * NI; idx += 256) {
        int z = idx / NI, i = idx - z * NI;
        float rho = (float)i * 0.01f;
        float w = kz2 * (rho * rho) * (float)z;
        float s, c;
        rsincos(w, &s, &c);
        sCS[z][i] = make_float2(c, s);
    }
    __syncthreads();

    // ---- Phase 3: plane[z][r] = pr^2 + pi^2 (2z x 4r register-tiled matmul) ----
    if (tid < 63) {
        int zt = tid / 9, rt = tid - zt * 9;
        int z0 = 2 * zt;
        int z1 = min(z0 + 1, NHALF - 1);
        int rb = 4 * rt;
        int r0 = min(rb,     NR - 1), r1 = min(rb + 1, NR - 1);
        int r2 = min(rb + 2, NR - 1), r3 = min(rb + 3, NR - 1);
        float pr[2][4] = {{0.f,0.f,0.f,0.f},{0.f,0.f,0.f,0.f}};
        float pi[2][4] = {{0.f,0.f,0.f,0.f},{0.f,0.f,0.f,0.f}};
        #pragma unroll 4
        for (int i = 0; i < NI; ++i) {
            float a0 = sA[r0][i], a1 = sA[r1][i], a2 = sA[r2][i], a3 = sA[r3][i];
            float2 c0 = sCS[z0][i];
            float2 c1 = sCS[z1][i];
            pr[0][0] = fmaf(a0, c0.x, pr[0][0]); pi[0][0] = fmaf(a0, c0.y, pi[0][0]);
            pr[0][1] = fmaf(a1, c0.x, pr[0][1]); pi[0][1] = fmaf(a1, c0.y, pi[0][1]);
            pr[0][2] = fmaf(a2, c0.x, pr[0][2]); pi[0][2] = fmaf(a2, c0.y, pi[0][2]);
            pr[0][3] = fmaf(a3, c0.x, pr[0][3]); pi[0][3] = fmaf(a3, c0.y, pi[0][3]);
            pr[1][0] = fmaf(a0, c1.x, pr[1][0]); pi[1][0] = fmaf(a0, c1.y, pi[1][0]);
            pr[1][1] = fmaf(a1, c1.x, pr[1][1]); pi[1][1] = fmaf(a1, c1.y, pi[1][1]);
            pr[1][2] = fmaf(a2, c1.x, pr[1][2]); pi[1][2] = fmaf(a2, c1.y, pi[1][2]);
            pr[1][3] = fmaf(a3, c1.x, pr[1][3]); pi[1][3] = fmaf(a3, c1.y, pi[1][3]);
        }
        #pragma unroll
        for (int zz = 0; zz < 2; ++zz) {
            int z = z0 + zz;
            if (z < NHALF) {
                #pragma unroll
                for (int j = 0; j < 4; ++j) {
                    int r = rb + j;
                    if (r < NR)
                        sPlane[z][r] = pr[zz][j] * pr[zz][j] + pi[zz][j] * pi[zz][j];
                }
            }
        }
    }
    __syncthreads();

    // ---- Phase 4: colsum[r] = plane[0][r] + 2*sum_{z=1..12} plane[z][r] (reflect z-weights) ----
    if (tid < NR) {
        float s = sPlane[0][tid];
        #pragma unroll
        for (int z = 1; z < NHALF; ++z) s += 2.0f * sPlane[z][tid];
        sCol[tid] = s;
    }
    __syncthreads();

    // ---- Phase 5: total = sum over (y,x) of radial interp of colsum ----
    float part = 0.0f;
    for (int pix = tid; pix < 625; pix += 256) {
        int yy = pix / 25, xx = pix - yy * 25;
        float dx = (float)(xx - 12), dy = (float)(yy - 12);
        float rp = sqrtf(dx * dx + dy * dy);
        int i1 = (int)floorf(rp * 2.0f);
        float d1 = (rp - 0.5f * (float)i1) * 2.0f;
        part += d1 * sCol[i1 + 1] + (1.0f - d1) * sCol[i1];
    }
    #pragma unroll
    for (int o = 16; o; o >>= 1) part += __shfl_down_sync(0xFFFFFFFFu, part, o);
    if ((tid & 31) == 0) sRed[tid >> 5] = part;
    __syncthreads();
    if (tid == 0) {
        float t = 0.0f;
        #pragma unroll
        for (int w = 0; w < 8; ++w) t += sRed[w];
        sInv = 1.0f / t;
    }
    __syncthreads();
    const float inv = sInv;

    // ---- Phase 6: write psf: interp 13 z-values once per (y,x), mirror to 25 z ----
    float* po = out + (size_t)p * 15625;
    for (int pix = tid; pix < 625; pix += 256) {
        int yy = pix / 25, xx = pix - yy * 25;
        float dx = (float)(xx - 12), dy = (float)(yy - 12);
        float rp = sqrtf(dx * dx + dy * dy);
        int i1 = (int)floorf(rp * 2.0f);
        float d1 = (rp - 0.5f * (float)i1) * 2.0f;
        float d2 = 1.0f - d1;
        float v[NHALF];
        #pragma unroll
        for (int zo = 0; zo < NHALF; ++zo)
            v[zo] = (d1 * sPlane[zo][i1 + 1] + d2 * sPlane[zo][i1]) * inv;
        #pragma unroll
        for (int z = 0; z < 25; ++z) {
            int zo = (z < 12) ? (12 - z) : (z - 12);
            po[z * 625 + pix] = v[zo];
        }
    }
}

extern "C" void kernel_launch(void* const* d_in, const int* in_sizes, int n_in,
                              void* d_out, int out_size) {
    const float* params = (const float*)d_in[0];
    float* out = (float*)d_out;
    int npairs = in_sizes[0] / 2;   // 16*64 = 1024
    bw_psf_kernel<<<npairs, 256>>>(params, out);
}

// round 2
// speedup vs baseline: 1.0614x; 1.0614x over previous
#include <cuda_runtime.h>
#include <math.h>

// Born-Wolf PSF: params (16,64,2) -> psf (16,64,25,25,25), normalized.
// One block per (b,c) pair.
//   A[i][r]  = J0(k n R[r] rho_i) * rho_i * trapw_i   (101 x 35, transposed, padded to 36)
//   CS[z][i] = (cos, sin)(0.5 k n^2 rho_i^2 z)        (13 x 101)
//   plane[z][r] = (sum_i A*cos)^2 + (sum_i A*sin)^2   (f32x2-packed matmul, 4 warps)
// then reflect-pad in z + radial bilinear interp + normalize.

#define NHALF 13
#define NR    35
#define NRP   36
#define NI    101

typedef unsigned long long ull;

// ---- f32x2 packed helpers (sm_100+) ----
__device__ __forceinline__ ull pack2(float lo, float hi) {
    ull r; asm("mov.b64 %0, {%1,%2};" : "=l"(r) : "f"(lo), "f"(hi)); return r;
}
__device__ __forceinline__ void unpack2(ull v, float& lo, float& hi) {
    asm("mov.b64 {%0,%1}, %2;" : "=f"(lo), "=f"(hi) : "l"(v));
}
__device__ __forceinline__ ull ffma2(ull a, ull b, ull c) {
    ull d; asm("fma.rn.f32x2 %0, %1, %2, %3;" : "=l"(d) : "l"(a), "l"(b), "l"(c)); return d;
}
__device__ __forceinline__ ull fmul2(ull a, ull b) {
    ull d; asm("mul.rn.f32x2 %0, %1, %2;" : "=l"(d) : "l"(a), "l"(b)); return d;
}
__device__ __forceinline__ ull fadd2(ull a, ull b) {
    ull d; asm("add.rn.f32x2 %0, %1, %2;" : "=l"(d) : "l"(a), "l"(b)); return d;
}
#define C2(c) pack2((c), (c))

// Accurate sincos for |x| up to ~1000: Cody-Waite 2-pi reduction + __sincosf.
__device__ __forceinline__ void rsincos(float x, float* s, float* c) {
    float q = rintf(x * 0.15915494309189535f);
    float r = fmaf(q, -6.28125f, x);
    r = fmaf(q, -1.9353071795864769e-3f, r);
    __sincosf(r, s, c);
}

// Scalar J0 (A&S rational approx, matches reference), fast divides.
__device__ __forceinline__ float bessel_j0f(float x) {
    float ax = fabsf(x);
    if (ax <= 8.0f) {
        float y = x * x;
        float num = -184.9052456f;
        num = fmaf(num, y, 77392.33017f);
        num = fmaf(num, y, -11214424.18f);
        num = fmaf(num, y, 651619640.7f);
        num = fmaf(num, y, -13362590354.0f);
        num = fmaf(num, y, 57568490574.0f);
        float den = y + 267.8532712f;
        den = fmaf(den, y, 59272.64853f);
        den = fmaf(den, y, 9494680.718f);
        den = fmaf(den, y, 1029532985.0f);
        den = fmaf(den, y, 57568490411.0f);
        return __fdividef(num, den);
    } else {
        float z = __fdividef(8.0f, ax);
        float y2 = z * z;
        float p1 = 0.2093887211e-6f;
        p1 = fmaf(p1, y2, -0.2073370639e-5f);
        p1 = fmaf(p1, y2, 0.2734510407e-4f);
        p1 = fmaf(p1, y2, -0.1098628627e-2f);
        p1 = fmaf(p1, y2, 1.0f);
        float p2 = -0.934935152e-7f;
        p2 = fmaf(p2, y2, 0.7621095161e-6f);
        p2 = fmaf(p2, y2, -0.6911147651e-5f);
        p2 = fmaf(p2, y2, 0.1430488765e-3f);
        p2 = fmaf(p2, y2, -0.1562499995e-1f);
        float s, c;
        rsincos(ax - 0.785398164f, &s, &c);
        return rsqrtf(ax) * 0.7978845608028654f * (c * p1 - z * s * p2);
    }
}

// Packed J0 for a pair of non-negative args (x0 <= x1).
__device__ __forceinline__ void j0_pair(float x0, float x1, float& r0, float& r1) {
    if (x1 <= 8.0f) {                       // both small
        ull x = pack2(x0, x1);
        ull y = fmul2(x, x);
        ull num = C2(-184.9052456f);
        num = ffma2(num, y, C2(77392.33017f));
        num = ffma2(num, y, C2(-11214424.18f));
        num = ffma2(num, y, C2(651619640.7f));
        num = ffma2(num, y, C2(-13362590354.0f));
        num = ffma2(num, y, C2(57568490574.0f));
        ull den = fadd2(y, C2(267.8532712f));
        den = ffma2(den, y, C2(59272.64853f));
        den = ffma2(den, y, C2(9494680.718f));
        den = ffma2(den, y, C2(1029532985.0f));
        den = ffma2(den, y, C2(57568490411.0f));
        float n0, n1, d0, d1;
        unpack2(num, n0, n1); unpack2(den, d0, d1);
        r0 = __fdividef(n0, d0);
        r1 = __fdividef(n1, d1);
    } else if (x0 > 8.0f) {                 // both large
        float z0 = __fdividef(8.0f, x0), z1 = __fdividef(8.0f, x1);
        ull z = pack2(z0, z1);
        ull y2 = fmul2(z, z);
        ull p1 = C2(0.2093887211e-6f);
        p1 = ffma2(p1, y2, C2(-0.2073370639e-5f));
        p1 = ffma2(p1, y2, C2(0.2734510407e-4f));
        p1 = ffma2(p1, y2, C2(-0.1098628627e-2f));
        p1 = ffma2(p1, y2, C2(1.0f));
        ull p2 = C2(-0.934935152e-7f);
        p2 = ffma2(p2, y2, C2(0.7621095161e-6f));
        p2 = ffma2(p2, y2, C2(-0.6911147651e-5f));
        p2 = ffma2(p2, y2, C2(0.1430488765e-3f));
        p2 = ffma2(p2, y2, C2(-0.1562499995e-1f));
        float p1a, p1b, p2a, p2b;
        unpack2(p1, p1a, p1b); unpack2(p2, p2a, p2b);
        float s0, c0, s1, c1;
        rsincos(x0 - 0.785398164f, &s0, &c0);
        rsincos(x1 - 0.785398164f, &s1, &c1);
        r0 = rsqrtf(x0) * 0.7978845608028654f * (c0 * p1a - z0 * s0 * p2a);
        r1 = rsqrtf(x1) * 0.7978845608028654f * (c1 * p1b - z1 * s1 * p2b);
    } else {                                // mixed (rare): scalar
        r0 = bessel_j0f(x0);
        r1 = bessel_j0f(x1);
    }
}

__global__ __launch_bounds__(256, 5)
void bw_psf_kernel(const float* __restrict__ params, float* __restrict__ out) {
    const int p = blockIdx.x;
    const int tid = threadIdx.x;

    __shared__ float  sA[NI][NRP];       // transposed J0 table, 14.5 KB
    __shared__ float2 sCS[NHALF][NI];    // 10.5 KB
    __shared__ float  sPlane[NHALF][NRP];
    __shared__ float  sCol[NRP];
    __shared__ float  sRed[8];
    __shared__ float  sInv;

    const float lam = fabsf(params[2 * p]);
    const float n   = fabsf(params[2 * p + 1]);
    const float k   = 6.2831853071795864769f / lam;
    const float kn  = k * n;
    const float kz2 = 0.5f * k * n * n;

    // ---- Phase 1: A[i][r] = J0(kn*(r/2)*rho_i) * rho_i * tw_i, pairs of i packed ----
    // jobs: r in [0,35) x ii in [0,51); i0 = 2*ii, i1 = min(i0+1, 100)
    for (int job = tid; job < NR * 51; job += 256) {
        int r = job / 51, ii = job - r * 51;
        int i0 = 2 * ii;
        int i1 = (i0 < NI - 1) ? i0 + 1 : NI - 1;
        float rr = kn * (0.5f * (float)r);
        float rho0 = (float)i0 * 0.01f, rho1 = (float)i1 * 0.01f;
        float j0a, j0b;
        j0_pair(rr * rho0, rr * rho1, j0a, j0b);
        float tw0 = (i0 == 0 || i0 == NI - 1) ? 0.005f : 0.01f;
        float tw1 = (i1 == NI - 1) ? 0.005f : 0.01f;
        sA[i0][r] = j0a * rho0 * tw0;
        if (i1 != i0) sA[i1][r] = j0b * rho1 * tw1;
    }
    // ---- Phase 2: CS[z][i] ----
    for (int idx = tid; idx < NHALF * NI; idx += 256) {
        int z = idx / NI, i = idx - z * NI;
        float rho = (float)i * 0.01f;
        float w = kz2 * (rho * rho) * (float)z;
        float s, c;
        rsincos(w, &s, &c);
        sCS[z][i] = make_float2(c, s);
    }
    __syncthreads();

    // ---- Phase 3: plane[z][r] via f32x2-packed matmul (117 threads = 4 warps) ----
    if (tid < NHALF * 9) {
        int z = tid / 9, rq = tid - z * 9;
        int r0 = rq * 4;
        ull re01 = 0, re23 = 0, im01 = 0, im23 = 0;  // (0.f,0.f) packs
        #pragma unroll 4
        for (int i = 0; i < NI; ++i) {
            float4 a = *(const float4*)&sA[i][r0];
            float2 cs = sCS[z][i];
            ull a01 = pack2(a.x, a.y), a23 = pack2(a.z, a.w);
            ull cc = pack2(cs.x, cs.x), ss = pack2(cs.y, cs.y);
            re01 = ffma2(a01, cc, re01);
            re23 = ffma2(a23, cc, re23);
            im01 = ffma2(a01, ss, im01);
            im23 = ffma2(a23, ss, im23);
        }
        float pr0, pr1, pr2, pr3, pi0, pi1, pi2, pi3;
        unpack2(re01, pr0, pr1); unpack2(re23, pr2, pr3);
        unpack2(im01, pi0, pi1); unpack2(im23, pi2, pi3);
        sPlane[z][r0]     = pr0 * pr0 + pi0 * pi0;
        sPlane[z][r0 + 1] = pr1 * pr1 + pi1 * pi1;
        sPlane[z][r0 + 2] = pr2 * pr2 + pi2 * pi2;
        if (r0 + 3 < NR) sPlane[z][r0 + 3] = pr3 * pr3 + pi3 * pi3;
    }
    __syncthreads();

    // ---- Phase 4: colsum[r] = plane[0][r] + 2*sum_{z>=1} plane[z][r] ----
    if (tid < NR) {
        float s = sPlane[0][tid];
        #pragma unroll
        for (int z = 1; z < NHALF; ++z) s += 2.0f * sPlane[z][tid];
        sCol[tid] = s;
    }
    __syncthreads();

    // ---- Phase 5: normalization sum over (y,x) ----
    float part = 0.0f;
    for (int pix = tid; pix < 625; pix += 256) {
        int yy = pix / 25, xx = pix - yy * 25;
        float dx = (float)(xx - 12), dy = (float)(yy - 12);
        float rp = sqrtf(dx * dx + dy * dy);
        int i1 = (int)floorf(rp * 2.0f);
        float d1 = (rp - 0.5f * (float)i1) * 2.0f;
        part += d1 * sCol[i1 + 1] + (1.0f - d1) * sCol[i1];
    }
    #pragma unroll
    for (int o = 16; o; o >>= 1) part += __shfl_down_sync(0xFFFFFFFFu, part, o);
    if ((tid & 31) == 0) sRed[tid >> 5] = part;
    __syncthreads();
    if (tid == 0) {
        float t = 0.0f;
        #pragma unroll
        for (int w = 0; w < 8; ++w) t += sRed[w];
        sInv = 1.0f / t;
    }
    __syncthreads();
    const float inv = sInv;

    // ---- Phase 6: interp 13 z-values per (y,x), mirror to 25 z ----
    float* po = out + (size_t)p * 15625;
    for (int pix = tid; pix < 625; pix += 256) {
        int yy = pix / 25, xx = pix - yy * 25;
        float dx = (float)(xx - 12), dy = (float)(yy - 12);
        float rp = sqrtf(dx * dx + dy * dy);
        int i1 = (int)floorf(rp * 2.0f);
        float d1 = (rp - 0.5f * (float)i1) * 2.0f;
        float d2 = 1.0f - d1;
        float v[NHALF];
        #pragma unroll
        for (int zo = 0; zo < NHALF; ++zo)
            v[zo] = (d1 * sPlane[zo][i1 + 1] + d2 * sPlane[zo][i1]) * inv;
        #pragma unroll
        for (int z = 0; z < 25; ++z) {
            int zo = (z < 12) ? (12 - z) : (z - 12);
            po[z * 625 + pix] = v[zo];
        }
    }
}

extern "C" void kernel_launch(void* const* d_in, const int* in_sizes, int n_in,
                              void* d_out, int out_size) {
    const float* params = (const float*)d_in[0];
    float* out = (float*)d_out;
    int npairs = in_sizes[0] / 2;   // 16*64 = 1024
    bw_psf_kernel<<<npairs, 256>>>(params, out);
}